// round 4
// baseline (speedup 1.0000x reference)
#include <cuda_runtime.h>
#include <cuda_fp16.h>

// ---------------------------------------------------------------------------
// SplatterPhongShader: N=4, H=256, W=256, K=4
// Pass 1: Phong shade + separable splat factors -> scratch (24B/element,
//         fp32 rgb + fp16 gaussian factors), mask-dtype probe inlined.
// Pass 2: 3x3 gather, 4-pixel y-strips per thread (halves scratch traffic),
//         depth-occlusion bucketing + compositing.
// ---------------------------------------------------------------------------

namespace cfg {
constexpr int NB = 4, HH = 256, WW = 256, KK = 4;
constexpr int NE   = NB * HH * WW * KK;   // 1,048,576 source elements
constexpr int NPIX = NB * HH * WW;        // 262,144 pixels
// (1+0.05) / (1 + 4*exp(-2) + 4*exp(-4))
constexpr float NORM_C = 0.6503143832f;
}

// Scratch, SoA by layer: [kk][pix]
__device__ float4 g_P[cfg::KK][cfg::NPIX];  // rgb0, rgb1, rgb2, half2(fy0,fy1)
__device__ uint2  g_Q[cfg::KK][cfg::NPIX];  // half2(fy2,fx0), half2(fx1,fx2)

static __device__ __forceinline__ unsigned pack2(float a, float b) {
    __half2 h = __floats2half2_rn(a, b);
    return *reinterpret_cast<unsigned*>(&h);
}
static __device__ __forceinline__ float lo_h(unsigned u) {
    return __half2float(__ushort_as_half((unsigned short)(u & 0xffffu)));
}
static __device__ __forceinline__ float hi_h(unsigned u) {
    return __half2float(__ushort_as_half((unsigned short)(u >> 16)));
}

// ---------------------------------------------------------------------------
// Pass 1: Phong shading + separable gaussian factors.
// Mask layout probe inlined: each warp scans the first 256 words of the mask
// (broadcast L1 hits). int32 mask words are 0/1; float32 words are
// 0/0x3f800000; packed-bool words (cumsum-monotone bytes, little-endian) are
// never 1 nor 0x3f800000 and nonzero ones are > 1. 256 words cover >= 64
// pixels -> P(all zero) ~ 1e-18, so classification is deterministic-safe.
// ---------------------------------------------------------------------------
__global__ __launch_bounds__(256)
void shade_kernel(const float* __restrict__ texels,
                  const float* __restrict__ normals,
                  const float* __restrict__ pcam,
                  const float* __restrict__ screen,
                  const void*  __restrict__ mask,
                  const float* __restrict__ Lp,
                  const float* __restrict__ la,
                  const float* __restrict__ ld,
                  const float* __restrict__ ls,
                  const float* __restrict__ Cp,
                  const float* __restrict__ ma,
                  const float* __restrict__ md,
                  const float* __restrict__ ms)
{
    const int e = blockIdx.x * blockDim.x + threadIdx.x;

    // ---- inline mask dtype probe (warp-uniform result) ----
    const int lid = threadIdx.x & 31;
    const uint4* mw = (const uint4*)mask;
    uint4 v0 = mw[lid * 2];
    uint4 v1 = mw[lid * 2 + 1];
    unsigned sawword = 0u, sawbyte = 0u;
    {
        const unsigned ws[8] = {v0.x, v0.y, v0.z, v0.w, v1.x, v1.y, v1.z, v1.w};
#pragma unroll
        for (int t = 0; t < 8; ++t) {
            unsigned w = ws[t];
            if (w == 1u || w == 0x3f800000u) sawword = 1u;
            else if (w > 1u) sawbyte = 1u;
        }
    }
    sawword = __ballot_sync(0xffffffffu, sawword);
    sawbyte = __ballot_sync(0xffffffffu, sawbyte);
    const bool byte_layout = (sawbyte != 0u) && (sawword == 0u);

    if (e >= cfg::NE) return;

    const int pix = e >> 2;
    const int kk  = e & 3;
    const int x = (e >> 2)  & 255;
    const int y = (e >> 10) & 255;

    // ---- mask -> alpha (exact 0/1) ----
    bool m;
    if (byte_layout) m = (((const unsigned char*)mask)[e] != 0);
    else             m = (((const unsigned int*)mask)[e]  != 0u);
    const float alpha = m ? 0.0f : 1.0f;

    // ---- Phong ----
    const float t0 = texels[3*e+0], t1 = texels[3*e+1], t2 = texels[3*e+2];
    float nx = normals[3*e+0], ny = normals[3*e+1], nz = normals[3*e+2];
    const float px = pcam[3*e+0], py = pcam[3*e+1], pz = pcam[3*e+2];

    float rin = rsqrtf(nx*nx + ny*ny + nz*nz + 1e-8f);
    nx *= rin; ny *= rin; nz *= rin;

    float lx = Lp[0] - px, ly = Lp[1] - py, lz = Lp[2] - pz;
    float ril = rsqrtf(lx*lx + ly*ly + lz*lz + 1e-8f);
    lx *= ril; ly *= ril; lz *= ril;

    float vx = Cp[0] - px, vy = Cp[1] - py, vz = Cp[2] - pz;
    float riv = rsqrtf(vx*vx + vy*vy + vz*vz + 1e-8f);
    vx *= riv; vy *= riv; vz *= riv;

    const float ndl = nx*lx + ny*ly + nz*lz;
    const float two_ndl = 2.0f * ndl;
    const float rx = two_ndl*nx - lx;
    const float ry = two_ndl*ny - ly;
    const float rz = two_ndl*nz - lz;
    float rdv = fmaxf(rx*vx + ry*vy + rz*vz, 0.0f);

    // rdv^64 by repeated squaring
    float s = rdv*rdv;  s = s*s;  s = s*s;  s = s*s;  s = s*s;  s = s*s;

    const float relndl = fmaxf(ndl, 0.0f);
    const float rgb0 = t0 * (la[0]*ma[0] + ld[0]*md[0]*relndl) + ls[0]*ms[0]*s;
    const float rgb1 = t1 * (la[1]*ma[1] + ld[1]*md[1]*relndl) + ls[1]*ms[1]*s;
    const float rgb2 = t2 * (la[2]*ma[2] + ld[2]*md[2]*relndl) + ls[2]*ms[2]*s;

    // ---- separable gaussian splat factors (2*sigma^2 = 0.5 -> coeff 2.0) ----
    const float2 sc = reinterpret_cast<const float2*>(screen)[e];
    const float jy = sc.x - ((float)y + 0.5f);
    const float jx = sc.y - ((float)x + 0.5f);
    const float na = cfg::NORM_C * alpha;

    const float fy0 = __expf(-2.0f * (jy + 1.0f) * (jy + 1.0f)) * na;
    const float fy1 = __expf(-2.0f *  jy         *  jy        ) * na;
    const float fy2 = __expf(-2.0f * (jy - 1.0f) * (jy - 1.0f)) * na;
    const float fx0 = __expf(-2.0f * (jx + 1.0f) * (jx + 1.0f));
    const float fx1 = __expf(-2.0f *  jx         *  jx        );
    const float fx2 = __expf(-2.0f * (jx - 1.0f) * (jx - 1.0f));

    g_P[kk][pix] = make_float4(rgb0, rgb1, rgb2,
                               __uint_as_float(pack2(fy0, fy1)));
    g_Q[kk][pix] = make_uint2(pack2(fy2, fx0), pack2(fx1, fx2));
}

// ---------------------------------------------------------------------------
// Pass 2: each thread composites a vertical strip of 4 output pixels.
// Sources: 6 rows x 3 cols shared across the strip -> scratch loads halved
// versus per-pixel gather, with lane-contiguous (coalesced) x addressing.
// ---------------------------------------------------------------------------
__global__ __launch_bounds__(128)
void blend_kernel(const float* __restrict__ qdepth, float* __restrict__ out)
{
    const int x  = blockIdx.x * 32 + threadIdx.x;
    const int ys = (blockIdx.y * 4 + threadIdx.y) * 4;   // strip start row
    const int n  = blockIdx.z;
    const int pixbase = (n * cfg::HH + ys) * cfg::WW + x;

    const float4* __restrict__ q4 = reinterpret_cast<const float4*>(qdepth);

    float4 qo[4];
#pragma unroll
    for (int i = 0; i < 4; ++i) qo[i] = q4[pixbase + i * cfg::WW];

    // acc[out][bucket*4 + ch]; buckets: 0=F(level<0), 1=S(==0), 2=B(>0)
    float acc[4][12];
#pragma unroll
    for (int i = 0; i < 4; ++i)
#pragma unroll
        for (int j = 0; j < 12; ++j) acc[i][j] = 0.f;

#pragma unroll
    for (int r = 0; r < 6; ++r) {
        const int sy = ys - 1 + r;
        if (sy < 0 || sy >= cfg::HH) continue;           // warp-uniform
        const int srow = (n * cfg::HH + sy) * cfg::WW;

#pragma unroll
        for (int o = -1; o <= 1; ++o) {
            const int sx = x + o;
            if ((unsigned)sx >= (unsigned)cfg::WW) continue;
            const int spix = srow + sx;
            const float4 pq = q4[spix];
            const float ptop = pq.x;

            // occ per affected output (yi in [r-2, r] ∩ [0,3])
            int occv[4];
#pragma unroll
            for (int yi = 0; yi < 4; ++yi) {
                if (yi < r - 2 || yi > r) continue;
                const float4 q = qo[yi];
                float dqm = fabsf(ptop - q.x); int lq = 0;
                { float a = fabsf(ptop - q.y); if (a < dqm) { dqm = a; lq = 1; } }
                { float a = fabsf(ptop - q.z); if (a < dqm) { dqm = a; lq = 2; } }
                { float a = fabsf(ptop - q.w); if (a < dqm) { dqm = a; lq = 3; } }
                const float q0 = q.x;
                float dpm = fabsf(q0 - pq.x); int lp = 0;
                { float a = fabsf(q0 - pq.y); if (a < dpm) { dpm = a; lp = 1; } }
                { float a = fabsf(q0 - pq.z); if (a < dpm) { dpm = a; lp = 2; } }
                { float a = fabsf(q0 - pq.w); if (a < dpm) { dpm = a; lp = 3; } }
                occv[yi] = (dqm <= dpm) ? lq : -lp;
            }

#pragma unroll
            for (int kk = 0; kk < cfg::KK; ++kk) {
                const float4 P  = g_P[kk][spix];
                const uint2  Qv = g_Q[kk][spix];
                const unsigned u01 = __float_as_uint(P.w);  // fy0, fy1
                // source at sx = x+o splats to x with dx = -o -> fx index 1-o
                const float fx = (o == -1) ? hi_h(Qv.y)     // fx2
                               : (o ==  0) ? lo_h(Qv.y)     // fx1
                                           : hi_h(Qv.x);    // fx0
                const float fyv[3] = { lo_h(u01), hi_h(u01), lo_h(Qv.x) };

#pragma unroll
                for (int yi = 0; yi < 4; ++yi) {
                    if (yi < r - 2 || yi > r) continue;
                    // dy = (ys+yi) - sy = yi - r + 1; fy index = dy+1
                    const float w = fyv[yi - r + 2] * fx;
                    const int lvl = kk + occv[yi];
                    float* a = acc[yi];
                    if (lvl < 0) {
                        a[0] = fmaf(P.x, w, a[0]);
                        a[1] = fmaf(P.y, w, a[1]);
                        a[2] = fmaf(P.z, w, a[2]);
                        a[3] += w;
                    } else if (lvl == 0) {
                        a[4] = fmaf(P.x, w, a[4]);
                        a[5] = fmaf(P.y, w, a[5]);
                        a[6] = fmaf(P.z, w, a[6]);
                        a[7] += w;
                    } else {
                        a[8]  = fmaf(P.x, w, a[8]);
                        a[9]  = fmaf(P.y, w, a[9]);
                        a[10] = fmaf(P.z, w, a[10]);
                        a[11] += w;
                    }
                }
            }
        }
    }

    // composite each strip pixel: bg, then surface, then foreground, then BG
#pragma unroll
    for (int yi = 0; yi < 4; ++yi) {
        const float* a = acc[yi];
        const float ib = 1.0f / fmaxf(a[11], 1e-10f);
        float o0 = a[8]*ib, o1 = a[9]*ib, o2 = a[10]*ib, o3 = a[11]*ib;

        const float is = 1.0f / fmaxf(a[7], 1e-10f);
        {
            const float s0 = a[4]*is, s1 = a[5]*is, s2 = a[6]*is, s3 = a[7]*is;
            const float om = 1.0f - s3;
            o0 = s0 + om*o0; o1 = s1 + om*o1; o2 = s2 + om*o2; o3 = s3 + om*o3;
        }
        const float iff = 1.0f / fmaxf(a[3], 1e-10f);
        {
            const float f0 = a[0]*iff, f1 = a[1]*iff, f2 = a[2]*iff, f3 = a[3]*iff;
            const float om = 1.0f - f3;
            o0 = f0 + om*o0; o1 = f1 + om*o1; o2 = f2 + om*o2; o3 = f3 + om*o3;
        }
        const float bgm = 1.0f - o3;
        reinterpret_cast<float4*>(out)[pixbase + yi * cfg::WW] =
            make_float4(o0 + bgm, o1 + bgm, o2 + bgm, o3);
    }
}

// ---------------------------------------------------------------------------
extern "C" void kernel_launch(void* const* d_in, const int* in_sizes, int n_in,
                              void* d_out, int out_size)
{
    const float* texels  = (const float*)d_in[0];
    const float* normals = (const float*)d_in[1];
    const float* pcam    = (const float*)d_in[2];
    const float* screen  = (const float*)d_in[3];
    const float* qdepth  = (const float*)d_in[4];
    const void*  mask    = d_in[5];
    const float* Lp      = (const float*)d_in[6];
    const float* la      = (const float*)d_in[7];
    const float* ld      = (const float*)d_in[8];
    const float* ls      = (const float*)d_in[9];
    const float* Cp      = (const float*)d_in[10];
    const float* ma      = (const float*)d_in[11];
    const float* md      = (const float*)d_in[12];
    const float* ms      = (const float*)d_in[13];
    float* out = (float*)d_out;

    shade_kernel<<<cfg::NE / 256, 256>>>(texels, normals, pcam, screen, mask,
                                         Lp, la, ld, ls, Cp, ma, md, ms);

    dim3 blk(32, 4, 1);
    dim3 grd(cfg::WW / 32, cfg::HH / 16, cfg::NB);  // 4-row strips, 4 strips/block
    blend_kernel<<<grd, blk>>>(qdepth, out);
}

// round 5
// speedup vs baseline: 1.2604x; 1.2604x over previous
#include <cuda_runtime.h>
#include <cuda_fp16.h>

// ---------------------------------------------------------------------------
// SplatterPhongShader: N=4, H=256, W=256, K=4
// Pass 1: Phong shade + separable splat factors -> scratch (24B/element).
// Pass 2: smem-tiled 3x3 gather: block loads 34x10 source halo (4 layers)
//         into shared memory cooperatively, then branchless depth-occlusion
//         bucketing + compositing per pixel.
// ---------------------------------------------------------------------------

namespace cfg {
constexpr int NB = 4, HH = 256, WW = 256, KK = 4;
constexpr int NE   = NB * HH * WW * KK;   // 1,048,576 source elements
constexpr int NPIX = NB * HH * WW;        // 262,144 pixels
// (1+0.05) / (1 + 4*exp(-2) + 4*exp(-4))
constexpr float NORM_C = 0.6503143832f;
}

// Scratch, SoA by layer: [kk][pix]
__device__ float4 g_P[cfg::KK][cfg::NPIX];  // rgb0, rgb1, rgb2, half2(fy0,fy1)
__device__ uint2  g_Q[cfg::KK][cfg::NPIX];  // half2(fy2,fx0), half2(fx1,fx2)

static __device__ __forceinline__ unsigned pack2(float a, float b) {
    __half2 h = __floats2half2_rn(a, b);
    return *reinterpret_cast<unsigned*>(&h);
}
static __device__ __forceinline__ float lo_h(unsigned u) {
    return __half2float(__ushort_as_half((unsigned short)(u & 0xffffu)));
}
static __device__ __forceinline__ float hi_h(unsigned u) {
    return __half2float(__ushort_as_half((unsigned short)(u >> 16)));
}

// ---------------------------------------------------------------------------
// Pass 1: Phong shading + separable gaussian factors (mask probe inlined).
// int32 mask words are 0/1; float32 words 0/0x3f800000; packed-bool words
// (cumsum-monotone bytes, LE) are never 1 nor 0x3f800000; nonzero ones > 1.
// ---------------------------------------------------------------------------
__global__ __launch_bounds__(256)
void shade_kernel(const float* __restrict__ texels,
                  const float* __restrict__ normals,
                  const float* __restrict__ pcam,
                  const float* __restrict__ screen,
                  const void*  __restrict__ mask,
                  const float* __restrict__ Lp,
                  const float* __restrict__ la,
                  const float* __restrict__ ld,
                  const float* __restrict__ ls,
                  const float* __restrict__ Cp,
                  const float* __restrict__ ma,
                  const float* __restrict__ md,
                  const float* __restrict__ ms)
{
    const int e = blockIdx.x * blockDim.x + threadIdx.x;

    // ---- inline mask dtype probe (warp-uniform result) ----
    const int lid = threadIdx.x & 31;
    const uint4* mw = (const uint4*)mask;
    uint4 v0 = mw[lid * 2];
    uint4 v1 = mw[lid * 2 + 1];
    unsigned sawword = 0u, sawbyte = 0u;
    {
        const unsigned ws[8] = {v0.x, v0.y, v0.z, v0.w, v1.x, v1.y, v1.z, v1.w};
#pragma unroll
        for (int t = 0; t < 8; ++t) {
            unsigned w = ws[t];
            if (w == 1u || w == 0x3f800000u) sawword = 1u;
            else if (w > 1u) sawbyte = 1u;
        }
    }
    sawword = __ballot_sync(0xffffffffu, sawword);
    sawbyte = __ballot_sync(0xffffffffu, sawbyte);
    const bool byte_layout = (sawbyte != 0u) && (sawword == 0u);

    if (e >= cfg::NE) return;

    const int pix = e >> 2;
    const int kk  = e & 3;
    const int x = (e >> 2)  & 255;
    const int y = (e >> 10) & 255;

    bool m;
    if (byte_layout) m = (((const unsigned char*)mask)[e] != 0);
    else             m = (((const unsigned int*)mask)[e]  != 0u);
    const float alpha = m ? 0.0f : 1.0f;

    // ---- Phong ----
    const float t0 = texels[3*e+0], t1 = texels[3*e+1], t2 = texels[3*e+2];
    float nx = normals[3*e+0], ny = normals[3*e+1], nz = normals[3*e+2];
    const float px = pcam[3*e+0], py = pcam[3*e+1], pz = pcam[3*e+2];

    float rin = rsqrtf(nx*nx + ny*ny + nz*nz + 1e-8f);
    nx *= rin; ny *= rin; nz *= rin;

    float lx = Lp[0] - px, ly = Lp[1] - py, lz = Lp[2] - pz;
    float ril = rsqrtf(lx*lx + ly*ly + lz*lz + 1e-8f);
    lx *= ril; ly *= ril; lz *= ril;

    float vx = Cp[0] - px, vy = Cp[1] - py, vz = Cp[2] - pz;
    float riv = rsqrtf(vx*vx + vy*vy + vz*vz + 1e-8f);
    vx *= riv; vy *= riv; vz *= riv;

    const float ndl = nx*lx + ny*ly + nz*lz;
    const float two_ndl = 2.0f * ndl;
    const float rx = two_ndl*nx - lx;
    const float ry = two_ndl*ny - ly;
    const float rz = two_ndl*nz - lz;
    float rdv = fmaxf(rx*vx + ry*vy + rz*vz, 0.0f);

    float s = rdv*rdv;  s = s*s;  s = s*s;  s = s*s;  s = s*s;  s = s*s;

    const float relndl = fmaxf(ndl, 0.0f);
    const float rgb0 = t0 * (la[0]*ma[0] + ld[0]*md[0]*relndl) + ls[0]*ms[0]*s;
    const float rgb1 = t1 * (la[1]*ma[1] + ld[1]*md[1]*relndl) + ls[1]*ms[1]*s;
    const float rgb2 = t2 * (la[2]*ma[2] + ld[2]*md[2]*relndl) + ls[2]*ms[2]*s;

    // ---- separable gaussian splat factors (2*sigma^2 = 0.5 -> coeff 2.0) ----
    const float2 sc = reinterpret_cast<const float2*>(screen)[e];
    const float jy = sc.x - ((float)y + 0.5f);
    const float jx = sc.y - ((float)x + 0.5f);
    const float na = cfg::NORM_C * alpha;

    const float fy0 = __expf(-2.0f * (jy + 1.0f) * (jy + 1.0f)) * na;
    const float fy1 = __expf(-2.0f *  jy         *  jy        ) * na;
    const float fy2 = __expf(-2.0f * (jy - 1.0f) * (jy - 1.0f)) * na;
    const float fx0 = __expf(-2.0f * (jx + 1.0f) * (jx + 1.0f));
    const float fx1 = __expf(-2.0f *  jx         *  jx        );
    const float fx2 = __expf(-2.0f * (jx - 1.0f) * (jx - 1.0f));

    g_P[kk][pix] = make_float4(rgb0, rgb1, rgb2,
                               __uint_as_float(pack2(fy0, fy1)));
    g_Q[kk][pix] = make_uint2(pack2(fy2, fx0), pack2(fx1, fx2));
}

// ---------------------------------------------------------------------------
// Pass 2: smem-tiled blend. Block = 32x8 pixels, halo = 34x10 sources.
// ---------------------------------------------------------------------------
__global__ __launch_bounds__(256, 4)
void blend_kernel(const float* __restrict__ qdepth, float* __restrict__ out)
{
    __shared__ float4 sQd[10][34];          //  5,440 B
    __shared__ float4 sP [cfg::KK][10][34]; // 21,760 B
    __shared__ uint2  sQ [cfg::KK][10][34]; // 10,880 B  (total 38,080 B)

    const int tx = threadIdx.x;             // 0..31
    const int ty = threadIdx.y;             // 0..7
    const int tid = ty * 32 + tx;
    const int x0 = blockIdx.x * 32;
    const int y0 = blockIdx.y * 8;
    const int n  = blockIdx.z;

    const float4* __restrict__ q4 = reinterpret_cast<const float4*>(qdepth);

    // ---- cooperative halo load: 340 source pixels x (qd + 4x(P,Q)) ----
#pragma unroll
    for (int i = tid; i < 340; i += 256) {
        const int r = i / 34, c = i % 34;
        const int gy = y0 - 1 + r;
        const int gx = x0 - 1 + c;
        const bool ok = ((unsigned)gy < (unsigned)cfg::HH) &&
                        ((unsigned)gx < (unsigned)cfg::WW);
        const int sp = (n * cfg::HH + gy) * cfg::WW + gx;
        sQd[r][c] = ok ? q4[sp] : make_float4(1e9f, 1e9f, 1e9f, 1e9f);
#pragma unroll
        for (int kk = 0; kk < cfg::KK; ++kk) {
            sP[kk][r][c] = ok ? g_P[kk][sp]
                             : make_float4(0.f, 0.f, 0.f, 0.f);
            sQ[kk][r][c] = ok ? g_Q[kk][sp] : make_uint2(0u, 0u);
        }
    }
    __syncthreads();

    // ---- per-pixel gather + branchless bucket accumulation ----
    const float4 qo = sQd[ty + 1][tx + 1];
    const float q0 = qo.x;

    float aF0=0.f,aF1=0.f,aF2=0.f,aF3=0.f;
    float aS0=0.f,aS1=0.f,aS2=0.f,aS3=0.f;
    float aB0=0.f,aB1=0.f,aB2=0.f,aB3=0.f;

#pragma unroll
    for (int dyy = 0; dyy < 3; ++dyy) {
#pragma unroll
        for (int dxx = 0; dxx < 3; ++dxx) {
            const float4 pq = sQd[ty + dyy][tx + dxx];
            const float ptop = pq.x;

            // lq/dq_min over own layers vs neighbor top
            float dqm = fabsf(ptop - qo.x); int lq = 0;
            { float a = fabsf(ptop - qo.y); if (a < dqm) { dqm = a; lq = 1; } }
            { float a = fabsf(ptop - qo.z); if (a < dqm) { dqm = a; lq = 2; } }
            { float a = fabsf(ptop - qo.w); if (a < dqm) { dqm = a; lq = 3; } }
            // lp/dp_min over neighbor layers vs own top
            float dpm = fabsf(q0 - pq.x); int lp = 0;
            { float a = fabsf(q0 - pq.y); if (a < dpm) { dpm = a; lp = 1; } }
            { float a = fabsf(q0 - pq.z); if (a < dpm) { dpm = a; lp = 2; } }
            { float a = fabsf(q0 - pq.w); if (a < dpm) { dpm = a; lp = 3; } }

            const int occ = (dqm <= dpm) ? lq : -lp;

#pragma unroll
            for (int kk = 0; kk < cfg::KK; ++kk) {
                const float4 P  = sP[kk][ty + dyy][tx + dxx];
                const uint2  Qv = sQ[kk][ty + dyy][tx + dxx];
                const unsigned u01 = __float_as_uint(P.w);  // (fy0, fy1)
                // fy index = 2-dyy : fy0=lo(u01) fy1=hi(u01) fy2=lo(Qv.x)
                const float fy = (dyy == 0) ? lo_h(Qv.x)
                               : (dyy == 1) ? hi_h(u01)
                                            : lo_h(u01);
                // fx index = 2-dxx : fx0=hi(Qv.x) fx1=lo(Qv.y) fx2=hi(Qv.y)
                const float fx = (dxx == 0) ? hi_h(Qv.y)
                               : (dxx == 1) ? lo_h(Qv.y)
                                            : hi_h(Qv.x);
                const float w = fy * fx;
                const int lvl = kk + occ;
                const float wF = (lvl < 0)  ? w : 0.f;
                const float wS = (lvl == 0) ? w : 0.f;
                const float wB = (lvl > 0)  ? w : 0.f;
                aF0 = fmaf(P.x, wF, aF0); aF1 = fmaf(P.y, wF, aF1);
                aF2 = fmaf(P.z, wF, aF2); aF3 += wF;
                aS0 = fmaf(P.x, wS, aS0); aS1 = fmaf(P.y, wS, aS1);
                aS2 = fmaf(P.z, wS, aS2); aS3 += wS;
                aB0 = fmaf(P.x, wB, aB0); aB1 = fmaf(P.y, wB, aB1);
                aB2 = fmaf(P.z, wB, aB2); aB3 += wB;
            }
        }
    }

    // ---- composite: bg, surface, foreground, then white background ----
    const float ib = 1.0f / fmaxf(aB3, 1e-10f);
    float o0 = aB0*ib, o1 = aB1*ib, o2 = aB2*ib, o3 = aB3*ib;

    const float is = 1.0f / fmaxf(aS3, 1e-10f);
    {
        const float s0 = aS0*is, s1 = aS1*is, s2 = aS2*is, s3 = aS3*is;
        const float om = 1.0f - s3;
        o0 = s0 + om*o0; o1 = s1 + om*o1; o2 = s2 + om*o2; o3 = s3 + om*o3;
    }
    const float iff = 1.0f / fmaxf(aF3, 1e-10f);
    {
        const float f0 = aF0*iff, f1 = aF1*iff, f2 = aF2*iff, f3 = aF3*iff;
        const float om = 1.0f - f3;
        o0 = f0 + om*o0; o1 = f1 + om*o1; o2 = f2 + om*o2; o3 = f3 + om*o3;
    }
    const float bgm = 1.0f - o3;
    const int pix = (n * cfg::HH + (y0 + ty)) * cfg::WW + (x0 + tx);
    reinterpret_cast<float4*>(out)[pix] =
        make_float4(o0 + bgm, o1 + bgm, o2 + bgm, o3);
}

// ---------------------------------------------------------------------------
extern "C" void kernel_launch(void* const* d_in, const int* in_sizes, int n_in,
                              void* d_out, int out_size)
{
    const float* texels  = (const float*)d_in[0];
    const float* normals = (const float*)d_in[1];
    const float* pcam    = (const float*)d_in[2];
    const float* screen  = (const float*)d_in[3];
    const float* qdepth  = (const float*)d_in[4];
    const void*  mask    = d_in[5];
    const float* Lp      = (const float*)d_in[6];
    const float* la      = (const float*)d_in[7];
    const float* ld      = (const float*)d_in[8];
    const float* ls      = (const float*)d_in[9];
    const float* Cp      = (const float*)d_in[10];
    const float* ma      = (const float*)d_in[11];
    const float* md      = (const float*)d_in[12];
    const float* ms      = (const float*)d_in[13];
    float* out = (float*)d_out;

    shade_kernel<<<cfg::NE / 256, 256>>>(texels, normals, pcam, screen, mask,
                                         Lp, la, ld, ls, Cp, ma, md, ms);

    dim3 blk(32, 8, 1);
    dim3 grd(cfg::WW / 32, cfg::HH / 8, cfg::NB);   // 1024 blocks
    blend_kernel<<<grd, blk>>>(qdepth, out);
}

// round 6
// speedup vs baseline: 1.4715x; 1.1675x over previous
#include <cuda_runtime.h>
#include <cuda_fp16.h>

// ---------------------------------------------------------------------------
// SplatterPhongShader: N=4, H=256, W=256, K=4 — FULLY FUSED single kernel.
// Each block owns a 32x8 output tile. It shades the 34x10 source-pixel halo
// (x4 layers = 1360 elements) directly into shared memory (fp32 rgb + fp16
// separable gaussian factors), then performs the 3x3 gather with depth-
// occlusion bucketing and compositing. No global scratch at all.
// ---------------------------------------------------------------------------

namespace cfg {
constexpr int NB = 4, HH = 256, WW = 256, KK = 4;
constexpr int NE = NB * HH * WW * KK;
// (1+0.05) / (1 + 4*exp(-2) + 4*exp(-4))
constexpr float NORM_C = 0.6503143832f;
constexpr int HR = 10, HC = 34;            // halo rows/cols (tile 8x32 + 1)
constexpr int HPIX = HR * HC;              // 340 halo pixels
constexpr int HELEM = HPIX * KK;           // 1360 halo elements
}

static __device__ __forceinline__ unsigned pack2(float a, float b) {
    __half2 h = __floats2half2_rn(a, b);
    return *reinterpret_cast<unsigned*>(&h);
}
static __device__ __forceinline__ float lo_h(unsigned u) {
    return __half2float(__ushort_as_half((unsigned short)(u & 0xffffu)));
}
static __device__ __forceinline__ float hi_h(unsigned u) {
    return __half2float(__ushort_as_half((unsigned short)(u >> 16)));
}

// ---------------------------------------------------------------------------
__global__ __launch_bounds__(256, 3)
void fused_kernel(const float* __restrict__ texels,
                  const float* __restrict__ normals,
                  const float* __restrict__ pcam,
                  const float* __restrict__ screen,
                  const float* __restrict__ qdepth,
                  const void*  __restrict__ mask,
                  const float* __restrict__ Lp,
                  const float* __restrict__ la,
                  const float* __restrict__ ld,
                  const float* __restrict__ ls,
                  const float* __restrict__ Cp,
                  const float* __restrict__ ma,
                  const float* __restrict__ md,
                  const float* __restrict__ ms,
                  float* __restrict__ out)
{
    __shared__ float4 sQd[cfg::HR][cfg::HC];            //  5,440 B
    __shared__ float4 sP [cfg::KK][cfg::HR][cfg::HC];   // 21,760 B
    __shared__ uint2  sQ [cfg::KK][cfg::HR][cfg::HC];   // 10,880 B

    const int tx = threadIdx.x;      // 0..31
    const int ty = threadIdx.y;      // 0..7
    const int tid = ty * 32 + tx;
    const int x0 = blockIdx.x * 32;
    const int y0 = blockIdx.y * 8;
    const int n  = blockIdx.z;

    const float4* __restrict__ q4 = reinterpret_cast<const float4*>(qdepth);

    // ---- mask dtype probe (warp-uniform; first 256 words, L1/L2 hits) ----
    const int lid = tid & 31;
    const uint4* mw = (const uint4*)mask;
    uint4 v0 = mw[lid * 2];
    uint4 v1 = mw[lid * 2 + 1];
    unsigned sawword = 0u, sawbyte = 0u;
    {
        const unsigned ws[8] = {v0.x, v0.y, v0.z, v0.w, v1.x, v1.y, v1.z, v1.w};
#pragma unroll
        for (int t = 0; t < 8; ++t) {
            unsigned w = ws[t];
            if (w == 1u || w == 0x3f800000u) sawword = 1u;
            else if (w > 1u) sawbyte = 1u;
        }
    }
    sawword = __ballot_sync(0xffffffffu, sawword);
    sawbyte = __ballot_sync(0xffffffffu, sawbyte);
    const bool byte_layout = (sawbyte != 0u) && (sawword == 0u);

    // ---- uniform lighting constants (L1-cached scalar loads) ----
    const float amb0 = la[0]*ma[0], amb1 = la[1]*ma[1], amb2 = la[2]*ma[2];
    const float dif0 = ld[0]*md[0], dif1 = ld[1]*md[1], dif2 = ld[2]*md[2];
    const float spc0 = ls[0]*ms[0], spc1 = ls[1]*ms[1], spc2 = ls[2]*ms[2];
    const float Lx = Lp[0], Ly = Lp[1], Lz = Lp[2];
    const float Cx = Cp[0], Cy = Cp[1], Cz = Cp[2];

    // ---- halo q-depth load (340 pixels) ----
#pragma unroll
    for (int i = tid; i < cfg::HPIX; i += 256) {
        const int r = i / cfg::HC, c = i % cfg::HC;
        const int gy = y0 - 1 + r, gx = x0 - 1 + c;
        const bool ok = ((unsigned)gy < (unsigned)cfg::HH) &&
                        ((unsigned)gx < (unsigned)cfg::WW);
        sQd[r][c] = ok ? q4[(n * cfg::HH + gy) * cfg::WW + gx]
                       : make_float4(1e9f, 1e9f, 1e9f, 1e9f);
    }

    // ---- shade the halo (1360 elements) directly into smem ----
#pragma unroll
    for (int h = tid; h < cfg::HELEM; h += 256) {
        const int kk = h & 3;
        const int hp = h >> 2;
        const int r = hp / cfg::HC, c = hp % cfg::HC;
        const int gy = y0 - 1 + r, gx = x0 - 1 + c;
        const bool ok = ((unsigned)gy < (unsigned)cfg::HH) &&
                        ((unsigned)gx < (unsigned)cfg::WW);
        if (!ok) {
            sP[kk][r][c] = make_float4(0.f, 0.f, 0.f, 0.f);
            sQ[kk][r][c] = make_uint2(0u, 0u);
            continue;
        }
        const int e = ((n * cfg::HH + gy) * cfg::WW + gx) * 4 + kk;

        bool mbit;
        if (byte_layout) mbit = (((const unsigned char*)mask)[e] != 0);
        else             mbit = (((const unsigned int*)mask)[e]  != 0u);
        const float alpha = mbit ? 0.0f : 1.0f;

        const float t0 = texels[3*e+0], t1 = texels[3*e+1], t2 = texels[3*e+2];
        float nx = normals[3*e+0], ny = normals[3*e+1], nz = normals[3*e+2];
        const float px = pcam[3*e+0], py = pcam[3*e+1], pz = pcam[3*e+2];

        float rin = rsqrtf(nx*nx + ny*ny + nz*nz + 1e-8f);
        nx *= rin; ny *= rin; nz *= rin;

        float lxx = Lx - px, lyy = Ly - py, lzz = Lz - pz;
        float ril = rsqrtf(lxx*lxx + lyy*lyy + lzz*lzz + 1e-8f);
        lxx *= ril; lyy *= ril; lzz *= ril;

        float vx = Cx - px, vy = Cy - py, vz = Cz - pz;
        float riv = rsqrtf(vx*vx + vy*vy + vz*vz + 1e-8f);
        vx *= riv; vy *= riv; vz *= riv;

        const float ndl = nx*lxx + ny*lyy + nz*lzz;
        const float tn = 2.0f * ndl;
        const float rx = tn*nx - lxx, ry = tn*ny - lyy, rz = tn*nz - lzz;
        float rdv = fmaxf(rx*vx + ry*vy + rz*vz, 0.0f);

        float s = rdv*rdv;  s = s*s;  s = s*s;  s = s*s;  s = s*s;  s = s*s;

        const float relndl = fmaxf(ndl, 0.0f);
        const float rgb0 = t0 * (amb0 + dif0*relndl) + spc0*s;
        const float rgb1 = t1 * (amb1 + dif1*relndl) + spc1*s;
        const float rgb2 = t2 * (amb2 + dif2*relndl) + spc2*s;

        const float2 sc = reinterpret_cast<const float2*>(screen)[e];
        const float jy = sc.x - ((float)gy + 0.5f);
        const float jx = sc.y - ((float)gx + 0.5f);
        const float na = cfg::NORM_C * alpha;

        const float fy0 = __expf(-2.0f * (jy + 1.0f) * (jy + 1.0f)) * na;
        const float fy1 = __expf(-2.0f *  jy         *  jy        ) * na;
        const float fy2 = __expf(-2.0f * (jy - 1.0f) * (jy - 1.0f)) * na;
        const float fx0 = __expf(-2.0f * (jx + 1.0f) * (jx + 1.0f));
        const float fx1 = __expf(-2.0f *  jx         *  jx        );
        const float fx2 = __expf(-2.0f * (jx - 1.0f) * (jx - 1.0f));

        sP[kk][r][c] = make_float4(rgb0, rgb1, rgb2,
                                   __uint_as_float(pack2(fy0, fy1)));
        sQ[kk][r][c] = make_uint2(pack2(fy2, fx0), pack2(fx1, fx2));
    }
    __syncthreads();

    // ---- per-pixel gather + branchless bucket accumulation ----
    const float4 qo = sQd[ty + 1][tx + 1];
    const float q0 = qo.x;

    float aF0=0.f,aF1=0.f,aF2=0.f,aF3=0.f;
    float aS0=0.f,aS1=0.f,aS2=0.f,aS3=0.f;
    float aB0=0.f,aB1=0.f,aB2=0.f,aB3=0.f;

#pragma unroll
    for (int dyy = 0; dyy < 3; ++dyy) {
#pragma unroll
        for (int dxx = 0; dxx < 3; ++dxx) {
            const float4 pq = sQd[ty + dyy][tx + dxx];
            const float ptop = pq.x;

            float dqm = fabsf(ptop - qo.x); int lq = 0;
            { float a = fabsf(ptop - qo.y); if (a < dqm) { dqm = a; lq = 1; } }
            { float a = fabsf(ptop - qo.z); if (a < dqm) { dqm = a; lq = 2; } }
            { float a = fabsf(ptop - qo.w); if (a < dqm) { dqm = a; lq = 3; } }
            float dpm = fabsf(q0 - pq.x); int lp = 0;
            { float a = fabsf(q0 - pq.y); if (a < dpm) { dpm = a; lp = 1; } }
            { float a = fabsf(q0 - pq.z); if (a < dpm) { dpm = a; lp = 2; } }
            { float a = fabsf(q0 - pq.w); if (a < dpm) { dpm = a; lp = 3; } }

            const int occ = (dqm <= dpm) ? lq : -lp;

#pragma unroll
            for (int kk = 0; kk < cfg::KK; ++kk) {
                const float4 P  = sP[kk][ty + dyy][tx + dxx];
                const uint2  Qv = sQ[kk][ty + dyy][tx + dxx];
                const unsigned u01 = __float_as_uint(P.w);  // (fy0, fy1)
                const float fy = (dyy == 0) ? lo_h(Qv.x)
                               : (dyy == 1) ? hi_h(u01)
                                            : lo_h(u01);
                const float fx = (dxx == 0) ? hi_h(Qv.y)
                               : (dxx == 1) ? lo_h(Qv.y)
                                            : hi_h(Qv.x);
                const float w = fy * fx;
                const int lvl = kk + occ;
                const float wF = (lvl < 0)  ? w : 0.f;
                const float wS = (lvl == 0) ? w : 0.f;
                const float wB = (lvl > 0)  ? w : 0.f;
                aF0 = fmaf(P.x, wF, aF0); aF1 = fmaf(P.y, wF, aF1);
                aF2 = fmaf(P.z, wF, aF2); aF3 += wF;
                aS0 = fmaf(P.x, wS, aS0); aS1 = fmaf(P.y, wS, aS1);
                aS2 = fmaf(P.z, wS, aS2); aS3 += wS;
                aB0 = fmaf(P.x, wB, aB0); aB1 = fmaf(P.y, wB, aB1);
                aB2 = fmaf(P.z, wB, aB2); aB3 += wB;
            }
        }
    }

    // ---- composite: bg, surface, foreground, then white background ----
    const float ib = 1.0f / fmaxf(aB3, 1e-10f);
    float o0 = aB0*ib, o1 = aB1*ib, o2 = aB2*ib, o3 = aB3*ib;

    const float is = 1.0f / fmaxf(aS3, 1e-10f);
    {
        const float s0 = aS0*is, s1 = aS1*is, s2 = aS2*is, s3 = aS3*is;
        const float om = 1.0f - s3;
        o0 = s0 + om*o0; o1 = s1 + om*o1; o2 = s2 + om*o2; o3 = s3 + om*o3;
    }
    const float iff = 1.0f / fmaxf(aF3, 1e-10f);
    {
        const float f0 = aF0*iff, f1 = aF1*iff, f2 = aF2*iff, f3 = aF3*iff;
        const float om = 1.0f - f3;
        o0 = f0 + om*o0; o1 = f1 + om*o1; o2 = f2 + om*o2; o3 = f3 + om*o3;
    }
    const float bgm = 1.0f - o3;
    const int pix = (n * cfg::HH + (y0 + ty)) * cfg::WW + (x0 + tx);
    reinterpret_cast<float4*>(out)[pix] =
        make_float4(o0 + bgm, o1 + bgm, o2 + bgm, o3);
}

// ---------------------------------------------------------------------------
extern "C" void kernel_launch(void* const* d_in, const int* in_sizes, int n_in,
                              void* d_out, int out_size)
{
    const float* texels  = (const float*)d_in[0];
    const float* normals = (const float*)d_in[1];
    const float* pcam    = (const float*)d_in[2];
    const float* screen  = (const float*)d_in[3];
    const float* qdepth  = (const float*)d_in[4];
    const void*  mask    = d_in[5];
    const float* Lp      = (const float*)d_in[6];
    const float* la      = (const float*)d_in[7];
    const float* ld      = (const float*)d_in[8];
    const float* ls      = (const float*)d_in[9];
    const float* Cp      = (const float*)d_in[10];
    const float* ma      = (const float*)d_in[11];
    const float* md      = (const float*)d_in[12];
    const float* ms      = (const float*)d_in[13];
    float* out = (float*)d_out;

    dim3 blk(32, 8, 1);
    dim3 grd(cfg::WW / 32, cfg::HH / 8, cfg::NB);   // 1024 blocks
    fused_kernel<<<grd, blk>>>(texels, normals, pcam, screen, qdepth, mask,
                               Lp, la, ld, ls, Cp, ma, md, ms, out);
}

// round 7
// speedup vs baseline: 1.5844x; 1.0767x over previous
#include <cuda_runtime.h>
#include <cuda_fp16.h>

// ---------------------------------------------------------------------------
// SplatterPhongShader: N=4, H=256, W=256, K=4 — fused single kernel.
// Block = 32x8 output tile; shades its 34x10x4 source halo into smem, then
// 3x3 gather with depth-occlusion bucketing + compositing.
// Round 7: launch_bounds(256,4) for 32 warps/SM + packed fma.rn.f32x2
// accumulation (2 FMAs per issue) in the blend hot loop.
// ---------------------------------------------------------------------------

namespace cfg {
constexpr int NB = 4, HH = 256, WW = 256, KK = 4;
// (1+0.05) / (1 + 4*exp(-2) + 4*exp(-4))
constexpr float NORM_C = 0.6503143832f;
constexpr int HR = 10, HC = 34;            // halo rows/cols (tile 8x32 + 1)
constexpr int HPIX = HR * HC;              // 340 halo pixels
constexpr int HELEM = HPIX * KK;           // 1360 halo elements
}

static __device__ __forceinline__ unsigned pack2(float a, float b) {
    __half2 h = __floats2half2_rn(a, b);
    return *reinterpret_cast<unsigned*>(&h);
}
static __device__ __forceinline__ float lo_h(unsigned u) {
    return __half2float(__ushort_as_half((unsigned short)(u & 0xffffu)));
}
static __device__ __forceinline__ float hi_h(unsigned u) {
    return __half2float(__ushort_as_half((unsigned short)(u >> 16)));
}

// ---- packed f32x2 helpers (Blackwell dual-lane FMA; PTX-only) ----
static __device__ __forceinline__ unsigned long long packf2(float lo, float hi) {
    unsigned long long r;
    asm("mov.b64 %0, {%1, %2};" : "=l"(r) : "f"(lo), "f"(hi));
    return r;
}
static __device__ __forceinline__ void fma2(unsigned long long& acc,
                                            unsigned long long ab,
                                            unsigned long long w2) {
    asm("fma.rn.f32x2 %0, %1, %2, %0;" : "+l"(acc) : "l"(ab), "l"(w2));
}
static __device__ __forceinline__ void unpackf2(unsigned long long v,
                                                float& lo, float& hi) {
    asm("mov.b64 {%0, %1}, %2;" : "=f"(lo), "=f"(hi) : "l"(v));
}

// ---------------------------------------------------------------------------
__global__ __launch_bounds__(256, 4)
void fused_kernel(const float* __restrict__ texels,
                  const float* __restrict__ normals,
                  const float* __restrict__ pcam,
                  const float* __restrict__ screen,
                  const float* __restrict__ qdepth,
                  const void*  __restrict__ mask,
                  const float* __restrict__ Lp,
                  const float* __restrict__ la,
                  const float* __restrict__ ld,
                  const float* __restrict__ ls,
                  const float* __restrict__ Cp,
                  const float* __restrict__ ma,
                  const float* __restrict__ md,
                  const float* __restrict__ ms,
                  float* __restrict__ out)
{
    __shared__ float4 sQd[cfg::HR][cfg::HC];            //  5,440 B
    __shared__ float4 sP [cfg::KK][cfg::HR][cfg::HC];   // 21,760 B
    __shared__ uint2  sQ [cfg::KK][cfg::HR][cfg::HC];   // 10,880 B

    const int tx = threadIdx.x;      // 0..31
    const int ty = threadIdx.y;      // 0..7
    const int tid = ty * 32 + tx;
    const int x0 = blockIdx.x * 32;
    const int y0 = blockIdx.y * 8;
    const int n  = blockIdx.z;

    const float4* __restrict__ q4 = reinterpret_cast<const float4*>(qdepth);

    // ---- mask dtype probe (warp-uniform; first 256 words, L1/L2 hits) ----
    const int lid = tid & 31;
    const uint4* mw = (const uint4*)mask;
    uint4 v0 = mw[lid * 2];
    uint4 v1 = mw[lid * 2 + 1];
    unsigned sawword = 0u, sawbyte = 0u;
    {
        const unsigned ws[8] = {v0.x, v0.y, v0.z, v0.w, v1.x, v1.y, v1.z, v1.w};
#pragma unroll
        for (int t = 0; t < 8; ++t) {
            unsigned w = ws[t];
            if (w == 1u || w == 0x3f800000u) sawword = 1u;
            else if (w > 1u) sawbyte = 1u;
        }
    }
    sawword = __ballot_sync(0xffffffffu, sawword);
    sawbyte = __ballot_sync(0xffffffffu, sawbyte);
    const bool byte_layout = (sawbyte != 0u) && (sawword == 0u);

    // ---- uniform lighting constants ----
    const float amb0 = la[0]*ma[0], amb1 = la[1]*ma[1], amb2 = la[2]*ma[2];
    const float dif0 = ld[0]*md[0], dif1 = ld[1]*md[1], dif2 = ld[2]*md[2];
    const float spc0 = ls[0]*ms[0], spc1 = ls[1]*ms[1], spc2 = ls[2]*ms[2];
    const float Lx = Lp[0], Ly = Lp[1], Lz = Lp[2];
    const float Cx = Cp[0], Cy = Cp[1], Cz = Cp[2];

    // ---- halo q-depth load (340 pixels) ----
#pragma unroll
    for (int i = tid; i < cfg::HPIX; i += 256) {
        const int r = i / cfg::HC, c = i % cfg::HC;
        const int gy = y0 - 1 + r, gx = x0 - 1 + c;
        const bool ok = ((unsigned)gy < (unsigned)cfg::HH) &&
                        ((unsigned)gx < (unsigned)cfg::WW);
        sQd[r][c] = ok ? q4[(n * cfg::HH + gy) * cfg::WW + gx]
                       : make_float4(1e9f, 1e9f, 1e9f, 1e9f);
    }

    // ---- shade the halo (1360 elements) directly into smem ----
#pragma unroll
    for (int h = tid; h < cfg::HELEM; h += 256) {
        const int kk = h & 3;
        const int hp = h >> 2;
        const int r = hp / cfg::HC, c = hp % cfg::HC;
        const int gy = y0 - 1 + r, gx = x0 - 1 + c;
        const bool ok = ((unsigned)gy < (unsigned)cfg::HH) &&
                        ((unsigned)gx < (unsigned)cfg::WW);
        if (!ok) {
            sP[kk][r][c] = make_float4(0.f, 0.f, 0.f, 0.f);
            sQ[kk][r][c] = make_uint2(0u, 0u);
            continue;
        }
        const int e = ((n * cfg::HH + gy) * cfg::WW + gx) * 4 + kk;

        bool mbit;
        if (byte_layout) mbit = (((const unsigned char*)mask)[e] != 0);
        else             mbit = (((const unsigned int*)mask)[e]  != 0u);
        const float alpha = mbit ? 0.0f : 1.0f;

        const float t0 = texels[3*e+0], t1 = texels[3*e+1], t2 = texels[3*e+2];
        float nx = normals[3*e+0], ny = normals[3*e+1], nz = normals[3*e+2];
        const float px = pcam[3*e+0], py = pcam[3*e+1], pz = pcam[3*e+2];

        float rin = rsqrtf(nx*nx + ny*ny + nz*nz + 1e-8f);
        nx *= rin; ny *= rin; nz *= rin;

        float lxx = Lx - px, lyy = Ly - py, lzz = Lz - pz;
        float ril = rsqrtf(lxx*lxx + lyy*lyy + lzz*lzz + 1e-8f);
        lxx *= ril; lyy *= ril; lzz *= ril;

        float vx = Cx - px, vy = Cy - py, vz = Cz - pz;
        float riv = rsqrtf(vx*vx + vy*vy + vz*vz + 1e-8f);
        vx *= riv; vy *= riv; vz *= riv;

        const float ndl = nx*lxx + ny*lyy + nz*lzz;
        const float tn = 2.0f * ndl;
        const float rx = tn*nx - lxx, ry = tn*ny - lyy, rz = tn*nz - lzz;
        float rdv = fmaxf(rx*vx + ry*vy + rz*vz, 0.0f);

        float s = rdv*rdv;  s = s*s;  s = s*s;  s = s*s;  s = s*s;  s = s*s;

        const float relndl = fmaxf(ndl, 0.0f);
        const float rgb0 = t0 * (amb0 + dif0*relndl) + spc0*s;
        const float rgb1 = t1 * (amb1 + dif1*relndl) + spc1*s;
        const float rgb2 = t2 * (amb2 + dif2*relndl) + spc2*s;

        const float2 sc = reinterpret_cast<const float2*>(screen)[e];
        const float jy = sc.x - ((float)gy + 0.5f);
        const float jx = sc.y - ((float)gx + 0.5f);
        const float na = cfg::NORM_C * alpha;

        const float fy0 = __expf(-2.0f * (jy + 1.0f) * (jy + 1.0f)) * na;
        const float fy1 = __expf(-2.0f *  jy         *  jy        ) * na;
        const float fy2 = __expf(-2.0f * (jy - 1.0f) * (jy - 1.0f)) * na;
        const float fx0 = __expf(-2.0f * (jx + 1.0f) * (jx + 1.0f));
        const float fx1 = __expf(-2.0f *  jx         *  jx        );
        const float fx2 = __expf(-2.0f * (jx - 1.0f) * (jx - 1.0f));

        sP[kk][r][c] = make_float4(rgb0, rgb1, rgb2,
                                   __uint_as_float(pack2(fy0, fy1)));
        sQ[kk][r][c] = make_uint2(pack2(fy2, fx0), pack2(fx1, fx2));
    }
    __syncthreads();

    // ---- per-pixel gather + packed-f32x2 bucket accumulation ----
    const float4 qo = sQd[ty + 1][tx + 1];
    const float q0 = qo.x;

    // (rgb0,rgb1) and (rgb2, sum_w) pairs per bucket; 0ull == (0.f, 0.f)
    unsigned long long F01 = 0ull, F2w = 0ull;
    unsigned long long S01 = 0ull, S2w = 0ull;
    unsigned long long B01 = 0ull, B2w = 0ull;

#pragma unroll
    for (int dyy = 0; dyy < 3; ++dyy) {
#pragma unroll
        for (int dxx = 0; dxx < 3; ++dxx) {
            const float4 pq = sQd[ty + dyy][tx + dxx];
            const float ptop = pq.x;

            float dqm = fabsf(ptop - qo.x); int lq = 0;
            { float a = fabsf(ptop - qo.y); if (a < dqm) { dqm = a; lq = 1; } }
            { float a = fabsf(ptop - qo.z); if (a < dqm) { dqm = a; lq = 2; } }
            { float a = fabsf(ptop - qo.w); if (a < dqm) { dqm = a; lq = 3; } }
            float dpm = fabsf(q0 - pq.x); int lp = 0;
            { float a = fabsf(q0 - pq.y); if (a < dpm) { dpm = a; lp = 1; } }
            { float a = fabsf(q0 - pq.z); if (a < dpm) { dpm = a; lp = 2; } }
            { float a = fabsf(q0 - pq.w); if (a < dpm) { dpm = a; lp = 3; } }

            // lvl = kk + occ; classify vs no = -occ
            const int no = (dqm <= dpm) ? -lq : lp;

#pragma unroll
            for (int kk = 0; kk < cfg::KK; ++kk) {
                const float4 P  = sP[kk][ty + dyy][tx + dxx];
                const uint2  Qv = sQ[kk][ty + dyy][tx + dxx];
                const unsigned u01 = __float_as_uint(P.w);  // (fy0, fy1)
                const float fy = (dyy == 0) ? lo_h(Qv.x)
                               : (dyy == 1) ? hi_h(u01)
                                            : lo_h(u01);
                const float fx = (dxx == 0) ? hi_h(Qv.y)
                               : (dxx == 1) ? lo_h(Qv.y)
                                            : hi_h(Qv.x);
                const float w = fy * fx;
                const float wF = (kk < no)  ? w : 0.f;
                const float wS = (kk == no) ? w : 0.f;
                const float wB = (kk > no)  ? w : 0.f;

                const unsigned long long Pxy = packf2(P.x, P.y);
                const unsigned long long Pz1 = packf2(P.z, 1.0f);
                const unsigned long long wF2 = packf2(wF, wF);
                const unsigned long long wS2 = packf2(wS, wS);
                const unsigned long long wB2 = packf2(wB, wB);

                fma2(F01, Pxy, wF2); fma2(F2w, Pz1, wF2);
                fma2(S01, Pxy, wS2); fma2(S2w, Pz1, wS2);
                fma2(B01, Pxy, wB2); fma2(B2w, Pz1, wB2);
            }
        }
    }

    float aF0, aF1, aF2, aF3, aS0, aS1, aS2, aS3, aB0, aB1, aB2, aB3;
    unpackf2(F01, aF0, aF1); unpackf2(F2w, aF2, aF3);
    unpackf2(S01, aS0, aS1); unpackf2(S2w, aS2, aS3);
    unpackf2(B01, aB0, aB1); unpackf2(B2w, aB2, aB3);

    // ---- composite: bg, surface, foreground, then white background ----
    const float ib = 1.0f / fmaxf(aB3, 1e-10f);
    float o0 = aB0*ib, o1 = aB1*ib, o2 = aB2*ib, o3 = aB3*ib;

    const float is = 1.0f / fmaxf(aS3, 1e-10f);
    {
        const float s0 = aS0*is, s1 = aS1*is, s2 = aS2*is, s3 = aS3*is;
        const float om = 1.0f - s3;
        o0 = s0 + om*o0; o1 = s1 + om*o1; o2 = s2 + om*o2; o3 = s3 + om*o3;
    }
    const float iff = 1.0f / fmaxf(aF3, 1e-10f);
    {
        const float f0 = aF0*iff, f1 = aF1*iff, f2 = aF2*iff, f3 = aF3*iff;
        const float om = 1.0f - f3;
        o0 = f0 + om*o0; o1 = f1 + om*o1; o2 = f2 + om*o2; o3 = f3 + om*o3;
    }
    const float bgm = 1.0f - o3;
    const int pix = (n * cfg::HH + (y0 + ty)) * cfg::WW + (x0 + tx);
    reinterpret_cast<float4*>(out)[pix] =
        make_float4(o0 + bgm, o1 + bgm, o2 + bgm, o3);
}

// ---------------------------------------------------------------------------
extern "C" void kernel_launch(void* const* d_in, const int* in_sizes, int n_in,
                              void* d_out, int out_size)
{
    const float* texels  = (const float*)d_in[0];
    const float* normals = (const float*)d_in[1];
    const float* pcam    = (const float*)d_in[2];
    const float* screen  = (const float*)d_in[3];
    const float* qdepth  = (const float*)d_in[4];
    const void*  mask    = d_in[5];
    const float* Lp      = (const float*)d_in[6];
    const float* la      = (const float*)d_in[7];
    const float* ld      = (const float*)d_in[8];
    const float* ls      = (const float*)d_in[9];
    const float* Cp      = (const float*)d_in[10];
    const float* ma      = (const float*)d_in[11];
    const float* md      = (const float*)d_in[12];
    const float* ms      = (const float*)d_in[13];
    float* out = (float*)d_out;

    dim3 blk(32, 8, 1);
    dim3 grd(cfg::WW / 32, cfg::HH / 8, cfg::NB);   // 1024 blocks
    fused_kernel<<<grd, blk>>>(texels, normals, pcam, screen, qdepth, mask,
                               Lp, la, ld, ls, Cp, ma, md, ms, out);
}